// round 4
// baseline (speedup 1.0000x reference)
#include <cuda_runtime.h>
#include <cuda_bf16.h>

// Problem constants
#define BB   256
#define NN   1000
#define D    128
#define H    8
#define NEGV (-1e9f)
#define TILE 32
#define PITCH 132   // floats; 132 % 32 == 4 -> conflict-free float4 row & column access

// Scratch (no allocs allowed)
__device__ float g_qkh[BB * H * D];   // per-batch per-head folded query vectors
__device__ float g_gk [BB * D];       // per-batch folded logit-key vector (incl. 1/sqrt(D))
__device__ int   g_mask_is_int;

// ---------------------------------------------------------------------------
// Kernel 0: detect mask storage format (bool bytes vs int32). Deterministic.
// If the first 256 little-endian words are all in {0,1}, it is int32; a byte
// mask of random 0/1 values fails this with prob ~1 - 8^-256.
// ---------------------------------------------------------------------------
__global__ void k_detect(const unsigned int* __restrict__ m) {
    int is_int = 1;
    #pragma unroll 1
    for (int i = 0; i < 256; ++i) {
        if (m[i] > 1u) { is_int = 0; break; }
    }
    g_mask_is_int = is_int;
}

__device__ __forceinline__ bool mask_at(const void* m, int idx, int is_int) {
    if (is_int) return ((const int*)m)[idx] != 0;
    return ((const unsigned char*)m)[idx] != 0;
}

// ---------------------------------------------------------------------------
// Kernel 1: per-batch precompute.
//   graph_embed = mean_n emb[b,n,:]
//   q = graph_embed @ W_fixed + [emb_first, emb_last] @ W_step
//   qKh[h,j] = sum_{d<16} q[h*16+d] * W_node[j, h*16+d]
// One CTA (256 threads) per batch. One full read of emb.
// ---------------------------------------------------------------------------
__global__ __launch_bounds__(256) void k_precompute(
    const float* __restrict__ emb,
    const float* __restrict__ Wf,     // [128,128]
    const float* __restrict__ Ws,     // [256,128]
    const float* __restrict__ Wn,     // [128,384]
    const int*   __restrict__ fidx,
    const int*   __restrict__ lidx)
{
    __shared__ float part[8][D];
    __shared__ float ge[D], ef[D], el[D];
    __shared__ float qpart[2][D];
    __shared__ float qv[D];

    const int b   = blockIdx.x;
    const int tid = threadIdx.x;
    const float* E = emb + (size_t)b * NN * D;

    // mean over N: 8 row-groups x 32 col-quads, float4 coalesced
    const int c4 = tid & 31;
    const int rg = tid >> 5;
    float4 acc = make_float4(0.f, 0.f, 0.f, 0.f);
    for (int r = rg; r < NN; r += 8) {
        float4 v = *(const float4*)(E + (size_t)r * D + c4 * 4);
        acc.x += v.x; acc.y += v.y; acc.z += v.z; acc.w += v.w;
    }
    ((float4*)part[rg])[c4] = acc;
    __syncthreads();

    if (tid < D) {
        float s = 0.f;
        #pragma unroll
        for (int g = 0; g < 8; ++g) s += part[g][tid];
        ge[tid] = s * (1.0f / NN);
        const int fi = fidx[b], li = lidx[b];
        ef[tid] = E[(size_t)fi * D + tid];
        el[tid] = E[(size_t)li * D + tid];
    }
    __syncthreads();

    // q projection: threads 0..127 do W_fixed part, 128..255 do W_step part
    {
        const int j = tid & 127;
        float a = 0.f;
        if (tid < D) {
            #pragma unroll 4
            for (int k = 0; k < D; ++k) a += ge[k] * Wf[k * D + j];
            qpart[0][j] = a;
        } else {
            #pragma unroll 4
            for (int k = 0; k < D; ++k) a += ef[k] * Ws[k * D + j];
            #pragma unroll 4
            for (int k = 0; k < D; ++k) a += el[k] * Ws[(D + k) * D + j];
            qpart[1][j] = a;
        }
    }
    __syncthreads();
    if (tid < D) qv[tid] = qpart[0][tid] + qpart[1][tid];
    __syncthreads();

    // qKh: thread j reads W_node row j cols [0,128)
    if (tid < D) {
        const float* wr = Wn + (size_t)tid * (3 * D);
        #pragma unroll
        for (int h = 0; h < H; ++h) {
            float a = 0.f;
            #pragma unroll
            for (int d4 = 0; d4 < 4; ++d4) {
                float4 w4 = *(const float4*)(wr + h * 16 + d4 * 4);
                a += qv[h * 16 + d4 * 4 + 0] * w4.x;
                a += qv[h * 16 + d4 * 4 + 1] * w4.y;
                a += qv[h * 16 + d4 * 4 + 2] * w4.z;
                a += qv[h * 16 + d4 * 4 + 3] * w4.w;
            }
            g_qkh[((size_t)b * H + h) * D + tid] = a;
        }
    }
}

// ---------------------------------------------------------------------------
// Kernel 2: flash-style masked multi-head glimpse + epilogue.
// One CTA (8 warps = 8 heads) per batch; one full read of emb.
// Online softmax per head; agg[h,:] = sum_n exp(compat-m) * emb[n,:].
// Epilogue: heads = (agg/s) @ Wn[:,D:2D]; glimpse = heads @ Wo;
//           gK = (glimpse @ Wn[:,2D:3D]^T) / sqrt(D).
// ---------------------------------------------------------------------------
__global__ __launch_bounds__(256) void k_glimpse(
    const float* __restrict__ emb,
    const float* __restrict__ Wn,
    const float* __restrict__ Wo,
    const void*  __restrict__ mask)
{
    __shared__ float tile[TILE * PITCH];   // also reused as agg_s[H][D] in epilogue
    __shared__ float qkh_s[H * D];
    __shared__ unsigned char mk[TILE];
    __shared__ float heads_s[D];
    __shared__ float glimpse_s[D];

    const int b    = blockIdx.x;
    const int tid  = threadIdx.x;
    const int wid  = tid >> 5;
    const int lane = tid & 31;
    const float* E = emb + (size_t)b * NN * D;
    const int mint = g_mask_is_int;

    for (int i = tid; i < H * D; i += 256) qkh_s[i] = g_qkh[(size_t)b * H * D + i];

    float  m = -3.0e38f, s = 0.f;
    float4 agg = make_float4(0.f, 0.f, 0.f, 0.f);

    for (int t = 0; t < NN; t += TILE) {
        const int rows = min(TILE, NN - t);
        __syncthreads();   // protect tile from previous iteration's readers
        // cooperative tile load (float4, coalesced; conflict-free smem stores)
        for (int i = tid; i < rows * 32; i += 256) {
            const int r = i >> 5, c = i & 31;
            *(float4*)&tile[r * PITCH + c * 4] =
                *(const float4*)(E + (size_t)(t + r) * D + c * 4);
        }
        if (tid < rows) {
            mk[tid] = mask_at(mask, b * NN + t + tid, mint) ? 1 : 0;
        }
        __syncthreads();

        // compat: warp = head, lane = row within tile
        float c = NEGV;
        if (lane < rows && !mk[lane]) {
            float a = 0.f;
            const float* er = &tile[lane * PITCH];
            const float* qh = &qkh_s[wid * D];
            #pragma unroll
            for (int j = 0; j < D; j += 4) {
                float4 e4 = *(const float4*)(er + j);
                float4 q4 = *(const float4*)(qh + j);  // broadcast
                a += e4.x * q4.x + e4.y * q4.y + e4.z * q4.z + e4.w * q4.w;
            }
            c = a * 0.25f;   // 1/sqrt(dk), dk=16
        }

        // online softmax update (per-warp scalars, all lanes identical)
        float tm = c;
        #pragma unroll
        for (int o = 16; o; o >>= 1) tm = fmaxf(tm, __shfl_xor_sync(0xffffffffu, tm, o));
        const float mnew = fmaxf(m, tm);
        const float corr = __expf(m - mnew);
        const float w    = __expf(c - mnew);   // 0 for masked/tail lanes
        float ws = w;
        #pragma unroll
        for (int o = 16; o; o >>= 1) ws += __shfl_xor_sync(0xffffffffu, ws, o);
        s = s * corr + ws;
        m = mnew;

        // agg accumulate: lane owns columns [4*lane, 4*lane+4)
        agg.x *= corr; agg.y *= corr; agg.z *= corr; agg.w *= corr;
        #pragma unroll 8
        for (int r = 0; r < rows; ++r) {
            const float wr = __shfl_sync(0xffffffffu, w, r);
            float4 e4 = *(const float4*)&tile[r * PITCH + lane * 4];  // conflict-free
            agg.x += wr * e4.x; agg.y += wr * e4.y;
            agg.z += wr * e4.z; agg.w += wr * e4.w;
        }
    }

    // ---- epilogue ----
    __syncthreads();
    const float inv = 1.0f / s;
    ((float4*)tile)[wid * 32 + lane] =
        make_float4(agg.x * inv, agg.y * inv, agg.z * inv, agg.w * inv);  // agg_s[h][j]
    __syncthreads();

    // heads[o] = sum_j agg_s[o/16][j] * Wn[j, 128 + o]   (coalesced Wn reads)
    if (tid < D) {
        const int h = tid >> 4;
        const float* as = &tile[h * D];
        float a = 0.f;
        #pragma unroll 4
        for (int j = 0; j < D; ++j) a += as[j] * Wn[(size_t)j * (3 * D) + D + tid];
        heads_s[tid] = a;
    }
    __syncthreads();

    // glimpse = heads @ Wo   (coalesced Wo reads)
    if (tid < D) {
        float a = 0.f;
        #pragma unroll 4
        for (int k = 0; k < D; ++k) a += heads_s[k] * Wo[k * D + tid];
        glimpse_s[tid] = a;
    }
    __syncthreads();

    // gK[j] = (sum_d glimpse[d] * Wn[j, 256 + d]) / sqrt(128)
    if (tid < D) {
        const float* wr = Wn + (size_t)tid * (3 * D) + 2 * D;
        float a = 0.f;
        #pragma unroll
        for (int dd = 0; dd < D; dd += 4) {
            float4 w4 = *(const float4*)(wr + dd);
            a += glimpse_s[dd + 0] * w4.x + glimpse_s[dd + 1] * w4.y
               + glimpse_s[dd + 2] * w4.z + glimpse_s[dd + 3] * w4.w;
        }
        g_gk[(size_t)b * D + tid] = a * 0.08838834764831845f;  // 1/sqrt(128)
    }
}

// ---------------------------------------------------------------------------
// Kernel 3: logits + log_softmax. One CTA (512 threads) per batch;
// one full read of emb. Deterministic smem tree reductions.
// ---------------------------------------------------------------------------
__global__ __launch_bounds__(512) void k_logits(
    const float* __restrict__ emb,
    const void*  __restrict__ mask,
    float*       __restrict__ out)
{
    __shared__ float lg[NN];
    __shared__ float gk_s[D];
    __shared__ float red[512];

    const int b    = blockIdx.x;
    const int tid  = threadIdx.x;
    const int wid  = tid >> 5;
    const int lane = tid & 31;
    const float* E = emb + (size_t)b * NN * D;
    const int mint = g_mask_is_int;

    if (tid < D) gk_s[tid] = g_gk[(size_t)b * D + tid];
    __syncthreads();
    const float4 g4 = *(const float4*)&gk_s[lane * 4];

    float wmax = -3.0e38f;
    for (int r = wid; r < NN; r += 16) {
        float4 e4 = *(const float4*)(E + (size_t)r * D + lane * 4);
        float p = e4.x * g4.x + e4.y * g4.y + e4.z * g4.z + e4.w * g4.w;
        #pragma unroll
        for (int o = 16; o; o >>= 1) p += __shfl_xor_sync(0xffffffffu, p, o);
        float v = tanhf(p) * 10.0f;
        if (mask_at(mask, b * NN + r, mint)) v = NEGV;
        if (lane == 0) lg[r] = v;
        wmax = fmaxf(wmax, v);
    }

    // block max (deterministic tree)
    red[tid] = wmax;
    __syncthreads();
    #pragma unroll
    for (int st = 256; st > 0; st >>= 1) {
        if (tid < st) red[tid] = fmaxf(red[tid], red[tid + st]);
        __syncthreads();
    }
    const float M = red[0];
    __syncthreads();

    // block sum of exp (deterministic tree)
    float se = 0.f;
    for (int r = tid; r < NN; r += 512) se += __expf(lg[r] - M);
    red[tid] = se;
    __syncthreads();
    #pragma unroll
    for (int st = 256; st > 0; st >>= 1) {
        if (tid < st) red[tid] += red[tid + st];
        __syncthreads();
    }
    const float lse = M + __logf(red[0]);

    for (int r = tid; r < NN; r += 512) out[b * NN + r] = lg[r] - lse;
}

// ---------------------------------------------------------------------------
// Launch. Inputs (metadata order): embeddings, W_node, W_fixed, W_step,
// W_out, first_idx, last_idx, mask. Output: float32 [256,1000].
// ---------------------------------------------------------------------------
extern "C" void kernel_launch(void* const* d_in, const int* in_sizes, int n_in,
                              void* d_out, int out_size)
{
    const float* emb  = (const float*)d_in[0];
    const float* Wn   = (const float*)d_in[1];
    const float* Wf   = (const float*)d_in[2];
    const float* Ws   = (const float*)d_in[3];
    const float* Wo   = (const float*)d_in[4];
    const int*   fi   = (const int*)d_in[5];
    const int*   li   = (const int*)d_in[6];
    const void*  mask = d_in[7];
    float*       out  = (float*)d_out;

    k_detect<<<1, 1>>>((const unsigned int*)mask);
    k_precompute<<<BB, 256>>>(emb, Wf, Ws, Wn, fi, li);
    k_glimpse<<<BB, 256>>>(emb, Wn, Wo, mask);
    k_logits<<<BB, 512>>>(emb, mask, out);
}

// round 8
// speedup vs baseline: 1.2479x; 1.2479x over previous
#include <cuda_runtime.h>
#include <cuda_bf16.h>

// Problem constants
#define BB   256
#define NN   1000
#define D    128
#define H    8
#define NEGV (-1e9f)
#define TILE 32
#define PITCH 132   // floats; conflict-free float4 row & column smem access

// Split factors (batch -> multiple CTAs for occupancy / memory parallelism)
#define SPM  8            // mean split     -> grid 2048
#define SPG  8            // glimpse split  -> grid 2048
#define SPL  4            // logits split   -> grid 1024
#define RPM  (NN/SPM)     // 125 rows per mean CTA
#define RPG  (NN/SPG)     // 125 rows per glimpse CTA
#define RPL  (NN/SPL)     // 250 rows per logits CTA

// Scratch (no allocs allowed) -- fully rewritten every call, no zeroing needed
__device__ float g_msum[BB * SPM * D];        // mean partial column sums   (1 MB)
__device__ float g_qkh [BB * H * D];          // folded per-head query vecs (1 MB)
__device__ float g_gm  [BB * SPG * H];        // glimpse partial max
__device__ float g_gs  [BB * SPG * H];        // glimpse partial sum
__device__ float g_gagg[BB * SPG * H * D];    // glimpse partial aggregates (4 MB)
__device__ float g_gk  [BB * D];              // folded logit key (incl 1/sqrt(D))
__device__ float g_lmax[BB * SPL];            // logits slice max
__device__ float g_lsum[BB * SPL];            // logits slice sum-exp
__device__ int   g_mask_is_int;

// ---------------------------------------------------------------------------
// Kernel 0: detect mask storage format (bool bytes vs int32). 256 parallel
// threads; benign write race on `bad` (all writers store 1). Deterministic.
// ---------------------------------------------------------------------------
__global__ void k_detect(const unsigned int* __restrict__ m) {
    __shared__ int bad;
    if (threadIdx.x == 0) bad = 0;
    __syncthreads();
    if (m[threadIdx.x] > 1u) bad = 1;
    __syncthreads();
    if (threadIdx.x == 0) g_mask_is_int = bad ? 0 : 1;
}

__device__ __forceinline__ bool mask_at(const void* m, int idx, int is_int) {
    if (is_int) return ((const int*)m)[idx] != 0;
    return ((const unsigned char*)m)[idx] != 0;
}

// ---------------------------------------------------------------------------
// Kernel 1a: mean partials. grid = BB*SPM. Each CTA streams 125 rows
// (16 independent float4 LDGs per thread) -> column-sum partial.
// ---------------------------------------------------------------------------
__global__ __launch_bounds__(256) void k_mean_part(const float* __restrict__ emb)
{
    __shared__ float part[8][D];
    const int bx  = blockIdx.x;
    const int b   = bx / SPM, p = bx % SPM;
    const int tid = threadIdx.x;
    const int c4  = tid & 31, rg = tid >> 5;
    const float* E = emb + (size_t)b * NN * D;
    const int r0 = p * RPM, r1 = r0 + RPM;

    float4 acc = make_float4(0.f, 0.f, 0.f, 0.f);
    for (int r = r0 + rg; r < r1; r += 8) {
        float4 v = *(const float4*)(E + (size_t)r * D + c4 * 4);
        acc.x += v.x; acc.y += v.y; acc.z += v.z; acc.w += v.w;
    }
    ((float4*)part[rg])[c4] = acc;
    __syncthreads();

    if (tid < D) {
        float s = 0.f;
        #pragma unroll
        for (int g = 0; g < 8; ++g) s += part[g][tid];
        g_msum[(size_t)bx * D + tid] = s;
    }
}

// ---------------------------------------------------------------------------
// Kernel 1b: fold mean partials, compute q and qKh. grid = BB, 256 thr.
// ---------------------------------------------------------------------------
__global__ __launch_bounds__(256) void k_qprep(
    const float* __restrict__ emb,
    const float* __restrict__ Wf,     // [128,128]
    const float* __restrict__ Ws,     // [256,128]
    const float* __restrict__ Wn,     // [128,384]
    const int*   __restrict__ fidx,
    const int*   __restrict__ lidx)
{
    __shared__ float ge[D], ef[D], el[D];
    __shared__ float qpart[2][D];
    __shared__ float qv[D];

    const int b   = blockIdx.x;
    const int tid = threadIdx.x;
    const float* E = emb + (size_t)b * NN * D;

    if (tid < D) {
        float sgm = 0.f;
        #pragma unroll
        for (int p = 0; p < SPM; ++p) sgm += g_msum[(size_t)(b * SPM + p) * D + tid];
        ge[tid] = sgm * (1.0f / NN);
        const int fi = fidx[b], li = lidx[b];
        ef[tid] = E[(size_t)fi * D + tid];
        el[tid] = E[(size_t)li * D + tid];
    }
    __syncthreads();

    // q projection: threads 0..127 do W_fixed part, 128..255 do W_step part
    {
        const int j = tid & 127;
        float a = 0.f;
        if (tid < D) {
            #pragma unroll 4
            for (int k = 0; k < D; ++k) a += ge[k] * Wf[k * D + j];
            qpart[0][j] = a;
        } else {
            #pragma unroll 4
            for (int k = 0; k < D; ++k) a += ef[k] * Ws[k * D + j];
            #pragma unroll 4
            for (int k = 0; k < D; ++k) a += el[k] * Ws[(D + k) * D + j];
            qpart[1][j] = a;
        }
    }
    __syncthreads();
    if (tid < D) qv[tid] = qpart[0][tid] + qpart[1][tid];
    __syncthreads();

    // qKh[h][j] = sum_{d<16} qv[h*16+d] * Wn[j, h*16+d]
    if (tid < D) {
        const float* wr = Wn + (size_t)tid * (3 * D);
        #pragma unroll
        for (int h = 0; h < H; ++h) {
            float a = 0.f;
            #pragma unroll
            for (int d4 = 0; d4 < 4; ++d4) {
                float4 w4 = *(const float4*)(wr + h * 16 + d4 * 4);
                a += qv[h * 16 + d4 * 4 + 0] * w4.x;
                a += qv[h * 16 + d4 * 4 + 1] * w4.y;
                a += qv[h * 16 + d4 * 4 + 2] * w4.z;
                a += qv[h * 16 + d4 * 4 + 3] * w4.w;
            }
            g_qkh[((size_t)b * H + h) * D + tid] = a;
        }
    }
}

// ---------------------------------------------------------------------------
// Kernel 2a: flash glimpse partials. grid = BB*SPG, 8 warps = 8 heads.
// Each CTA does 125 rows of its batch; writes (m, s, agg[128]) per head.
// All-masked slices produce m=-1e9 partials that merge to exactly zero.
// ---------------------------------------------------------------------------
__global__ __launch_bounds__(256) void k_glimpse_part(
    const float* __restrict__ emb,
    const void*  __restrict__ mask)
{
    __shared__ float tile[TILE * PITCH];
    __shared__ float qkh_s[H * D];
    __shared__ unsigned char mk[TILE];

    const int bx   = blockIdx.x;
    const int b    = bx / SPG, c = bx % SPG;
    const int tid  = threadIdx.x;
    const int wid  = tid >> 5;
    const int lane = tid & 31;
    const float* E = emb + (size_t)b * NN * D;
    const int mint = g_mask_is_int;
    const int r0 = c * RPG, r1 = r0 + RPG;

    for (int i = tid; i < H * D; i += 256) qkh_s[i] = g_qkh[(size_t)b * H * D + i];

    float  m = -3.0e38f, s = 0.f;
    float4 agg = make_float4(0.f, 0.f, 0.f, 0.f);

    for (int t = r0; t < r1; t += TILE) {
        const int rows = min(TILE, r1 - t);
        __syncthreads();
        for (int i = tid; i < rows * 32; i += 256) {
            const int r = i >> 5, cc = i & 31;
            *(float4*)&tile[r * PITCH + cc * 4] =
                *(const float4*)(E + (size_t)(t + r) * D + cc * 4);
        }
        if (tid < rows) mk[tid] = mask_at(mask, b * NN + t + tid, mint) ? 1 : 0;
        __syncthreads();

        // compat: warp = head, lane = row within tile
        float cv = NEGV;
        if (lane < rows && !mk[lane]) {
            float a = 0.f;
            const float* er = &tile[lane * PITCH];
            const float* qh = &qkh_s[wid * D];
            #pragma unroll
            for (int j = 0; j < D; j += 4) {
                float4 e4 = *(const float4*)(er + j);
                float4 q4 = *(const float4*)(qh + j);  // broadcast, conflict-free
                a += e4.x * q4.x + e4.y * q4.y + e4.z * q4.z + e4.w * q4.w;
            }
            cv = a * 0.25f;   // 1/sqrt(dk), dk=16
        }

        // online softmax (per-warp scalars)
        float tm = cv;
        #pragma unroll
        for (int o = 16; o; o >>= 1) tm = fmaxf(tm, __shfl_xor_sync(0xffffffffu, tm, o));
        const float mnew = fmaxf(m, tm);
        const float corr = __expf(m - mnew);
        const float w    = __expf(cv - mnew);
        float ws = w;
        #pragma unroll
        for (int o = 16; o; o >>= 1) ws += __shfl_xor_sync(0xffffffffu, ws, o);
        s = s * corr + ws;
        m = mnew;

        agg.x *= corr; agg.y *= corr; agg.z *= corr; agg.w *= corr;
        #pragma unroll 8
        for (int r = 0; r < rows; ++r) {
            const float wr = __shfl_sync(0xffffffffu, w, r);
            float4 e4 = *(const float4*)&tile[r * PITCH + lane * 4];  // conflict-free
            agg.x += wr * e4.x; agg.y += wr * e4.y;
            agg.z += wr * e4.z; agg.w += wr * e4.w;
        }
    }

    if (lane == 0) { g_gm[bx * H + wid] = m; g_gs[bx * H + wid] = s; }
    *(float4*)&g_gagg[((size_t)bx * H + wid) * D + lane * 4] = agg;
}

// ---------------------------------------------------------------------------
// Kernel 2b: merge glimpse partials + epilogue. grid = BB, 128 threads.
// heads = (agg/S) @ Wn[:,D:2D]; glimpse = heads @ Wo;
// gK = (glimpse @ Wn[:,2D:3D]^T) / sqrt(D).
// ---------------------------------------------------------------------------
__global__ __launch_bounds__(128) void k_gmerge(
    const float* __restrict__ Wn,
    const float* __restrict__ Wo)
{
    __shared__ float Ms[H], Ss[H], e_s[SPG][H];
    __shared__ float aggs[H * D];
    __shared__ float heads_s[D];
    __shared__ float glimpse_s[D];

    const int b = blockIdx.x, tid = threadIdx.x;

    if (tid < H) {
        float M = -3.0e38f;
        #pragma unroll
        for (int c = 0; c < SPG; ++c) M = fmaxf(M, g_gm[(b * SPG + c) * H + tid]);
        Ms[tid] = M;
    }
    __syncthreads();
    if (tid < SPG * H) {
        const int c = tid >> 3, h = tid & 7;
        e_s[c][h] = __expf(g_gm[(b * SPG + c) * H + h] - Ms[h]);
    }
    __syncthreads();
    if (tid < H) {
        float S = 0.f;
        #pragma unroll
        for (int c = 0; c < SPG; ++c) S += g_gs[(b * SPG + c) * H + tid] * e_s[c][tid];
        Ss[tid] = S;
    }
    __syncthreads();

    #pragma unroll
    for (int h = 0; h < H; ++h) {
        float a = 0.f;
        #pragma unroll
        for (int c = 0; c < SPG; ++c)
            a += g_gagg[((size_t)(b * SPG + c) * H + h) * D + tid] * e_s[c][h];
        aggs[h * D + tid] = a / Ss[h];
    }
    __syncthreads();

    // heads[o] = sum_j aggs[o/16][j] * Wn[j, 128 + o]
    {
        const int h = tid >> 4;
        const float* as = &aggs[h * D];
        float a = 0.f;
        #pragma unroll 4
        for (int j = 0; j < D; ++j) a += as[j] * Wn[(size_t)j * (3 * D) + D + tid];
        heads_s[tid] = a;
    }
    __syncthreads();

    {
        float a = 0.f;
        #pragma unroll 4
        for (int k = 0; k < D; ++k) a += heads_s[k] * Wo[k * D + tid];
        glimpse_s[tid] = a;
    }
    __syncthreads();

    {
        const float* wr = Wn + (size_t)tid * (3 * D) + 2 * D;
        float a = 0.f;
        #pragma unroll
        for (int dd = 0; dd < D; dd += 4) {
            float4 w4 = *(const float4*)(wr + dd);
            a += glimpse_s[dd + 0] * w4.x + glimpse_s[dd + 1] * w4.y
               + glimpse_s[dd + 2] * w4.z + glimpse_s[dd + 3] * w4.w;
        }
        g_gk[(size_t)b * D + tid] = a * 0.08838834764831845f;  // 1/sqrt(128)
    }
}

// ---------------------------------------------------------------------------
// Kernel 3a: logits slices. grid = BB*SPL, 256 thr (8 warps, 2 rows in
// flight per warp). Writes raw logits to out + per-slice (max, sum-exp).
// ---------------------------------------------------------------------------
__global__ __launch_bounds__(256) void k_logits_part(
    const float* __restrict__ emb,
    const void*  __restrict__ mask,
    float*       __restrict__ out)
{
    __shared__ float gk_s[D];
    __shared__ float lg[RPL];
    __shared__ float red[256];

    const int bx   = blockIdx.x;
    const int b    = bx / SPL, c = bx % SPL;
    const int tid  = threadIdx.x;
    const int wid  = tid >> 5;
    const int lane = tid & 31;
    const int base = c * RPL;
    const float* E = emb + (size_t)b * NN * D;
    const int mint = g_mask_is_int;

    if (tid < D) gk_s[tid] = g_gk[(size_t)b * D + tid];
    __syncthreads();
    const float4 g4 = *(const float4*)&gk_s[lane * 4];

    float wmax = -3.0e38f;
    for (int k = wid; k < RPL; k += 16) {
        const int  k2   = k + 8;
        const bool has2 = (k2 < RPL);
        float4 e1 = *(const float4*)(E + (size_t)(base + k) * D + lane * 4);
        float4 e2 = has2 ? *(const float4*)(E + (size_t)(base + k2) * D + lane * 4)
                         : make_float4(0.f, 0.f, 0.f, 0.f);
        float p1 = e1.x * g4.x + e1.y * g4.y + e1.z * g4.z + e1.w * g4.w;
        float p2 = e2.x * g4.x + e2.y * g4.y + e2.z * g4.z + e2.w * g4.w;
        #pragma unroll
        for (int o = 16; o; o >>= 1) {
            p1 += __shfl_xor_sync(0xffffffffu, p1, o);
            p2 += __shfl_xor_sync(0xffffffffu, p2, o);
        }
        float v1 = tanhf(p1) * 10.0f;
        if (mask_at(mask, b * NN + base + k, mint)) v1 = NEGV;
        wmax = fmaxf(wmax, v1);
        if (lane == 0) lg[k] = v1;
        if (has2) {
            float v2 = tanhf(p2) * 10.0f;
            if (mask_at(mask, b * NN + base + k2, mint)) v2 = NEGV;
            wmax = fmaxf(wmax, v2);
            if (lane == 0) lg[k2] = v2;
        }
    }

    red[tid] = wmax;
    __syncthreads();
    #pragma unroll
    for (int st = 128; st > 0; st >>= 1) {
        if (tid < st) red[tid] = fmaxf(red[tid], red[tid + st]);
        __syncthreads();
    }
    const float M = red[0];
    __syncthreads();

    red[tid] = (tid < RPL) ? __expf(lg[tid] - M) : 0.f;   // RPL=250 <= 256
    __syncthreads();
    #pragma unroll
    for (int st = 128; st > 0; st >>= 1) {
        if (tid < st) red[tid] += red[tid + st];
        __syncthreads();
    }

    if (tid == 0) { g_lmax[bx] = M; g_lsum[bx] = red[0]; }
    for (int i = tid; i < RPL; i += 256) out[b * NN + base + i] = lg[i];
}

// ---------------------------------------------------------------------------
// Kernel 3b: fold slice (max, sum) into lse; subtract in-place. grid = BB.
// ---------------------------------------------------------------------------
__global__ __launch_bounds__(256) void k_fix(float* __restrict__ out)
{
    __shared__ float lse_s;
    const int b = blockIdx.x, tid = threadIdx.x;
    if (tid == 0) {
        float M = -3.0e38f;
        #pragma unroll
        for (int c = 0; c < SPL; ++c) M = fmaxf(M, g_lmax[b * SPL + c]);
        float S = 0.f;
        #pragma unroll
        for (int c = 0; c < SPL; ++c) S += g_lsum[b * SPL + c] * __expf(g_lmax[b * SPL + c] - M);
        lse_s = M + __logf(S);
    }
    __syncthreads();
    const float lse = lse_s;
    for (int i = tid; i < NN; i += 256) out[b * NN + i] -= lse;
}

// ---------------------------------------------------------------------------
// Launch. Inputs (metadata order): embeddings, W_node, W_fixed, W_step,
// W_out, first_idx, last_idx, mask. Output: float32 [256,1000].
// ---------------------------------------------------------------------------
extern "C" void kernel_launch(void* const* d_in, const int* in_sizes, int n_in,
                              void* d_out, int out_size)
{
    const float* emb  = (const float*)d_in[0];
    const float* Wn   = (const float*)d_in[1];
    const float* Wf   = (const float*)d_in[2];
    const float* Ws   = (const float*)d_in[3];
    const float* Wo   = (const float*)d_in[4];
    const int*   fi   = (const int*)d_in[5];
    const int*   li   = (const int*)d_in[6];
    const void*  mask = d_in[7];
    float*       out  = (float*)d_out;

    k_detect      <<<1, 256>>>((const unsigned int*)mask);
    k_mean_part   <<<BB * SPM, 256>>>(emb);
    k_qprep       <<<BB, 256>>>(emb, Wf, Ws, Wn, fi, li);
    k_glimpse_part<<<BB * SPG, 256>>>(emb, mask);
    k_gmerge      <<<BB, 128>>>(Wn, Wo);
    k_logits_part <<<BB * SPL, 256>>>(emb, mask, out);
    k_fix         <<<BB, 256>>>(out);
}

// round 9
// speedup vs baseline: 1.4484x; 1.1607x over previous
#include <cuda_runtime.h>
#include <cuda_bf16.h>

// Problem constants
#define BB   256
#define NN   1000
#define D    128
#define H    8
#define NEGV (-1e9f)

// Split factors (batch -> multiple CTAs for occupancy / memory parallelism)
#define SPM  8            // mean split     -> grid 2048
#define SPG  8            // glimpse split  -> grid 2048
#define SPL  4            // logits split   -> grid 1024
#define RPM  (NN/SPM)     // 125 rows per mean CTA
#define RPG  (NN/SPG)     // 125 rows per glimpse CTA
#define RPL  (NN/SPL)     // 250 rows per logits CTA

// Scratch (no allocs allowed) -- fully rewritten every call, no zeroing needed
__device__ float g_msum[BB * SPM * D];        // mean partial column sums   (1 MB)
__device__ float g_qkh [BB * H * D];          // folded per-head query vecs (1 MB)
__device__ float g_gm  [BB * SPG * H];        // glimpse partial max
__device__ float g_gs  [BB * SPG * H];        // glimpse partial sum
__device__ float g_gagg[BB * SPG * H * D];    // glimpse partial aggregates (4 MB)
__device__ float g_gk  [BB * D];              // folded logit key (incl 1/sqrt(D))
__device__ float g_lmax[BB * SPL];            // logits slice max
__device__ float g_lsum[BB * SPL];            // logits slice sum-exp
__device__ int   g_mask_is_int;

// ---------------------------------------------------------------------------
// Kernel 0: detect mask storage format (bool bytes vs int32). Deterministic.
// ---------------------------------------------------------------------------
__global__ void k_detect(const unsigned int* __restrict__ m) {
    __shared__ int bad;
    if (threadIdx.x == 0) bad = 0;
    __syncthreads();
    if (m[threadIdx.x] > 1u) bad = 1;
    __syncthreads();
    if (threadIdx.x == 0) g_mask_is_int = bad ? 0 : 1;
}

__device__ __forceinline__ bool mask_at(const void* m, int idx, int is_int) {
    if (is_int) return ((const int*)m)[idx] != 0;
    return ((const unsigned char*)m)[idx] != 0;
}

// ---------------------------------------------------------------------------
// Kernel 1a: mean partials. grid = BB*SPM.
// ---------------------------------------------------------------------------
__global__ __launch_bounds__(256) void k_mean_part(const float* __restrict__ emb)
{
    __shared__ float part[8][D];
    const int bx  = blockIdx.x;
    const int b   = bx / SPM, p = bx % SPM;
    const int tid = threadIdx.x;
    const int c4  = tid & 31, rg = tid >> 5;
    const float* E = emb + (size_t)b * NN * D;
    const int r0 = p * RPM, r1 = r0 + RPM;

    float4 acc = make_float4(0.f, 0.f, 0.f, 0.f);
    for (int r = r0 + rg; r < r1; r += 8) {
        float4 v = *(const float4*)(E + (size_t)r * D + c4 * 4);
        acc.x += v.x; acc.y += v.y; acc.z += v.z; acc.w += v.w;
    }
    ((float4*)part[rg])[c4] = acc;
    __syncthreads();

    if (tid < D) {
        float s = 0.f;
        #pragma unroll
        for (int g = 0; g < 8; ++g) s += part[g][tid];
        g_msum[(size_t)bx * D + tid] = s;
    }
}

// ---------------------------------------------------------------------------
// Kernel 1b: fold mean partials, compute q and qKh. grid = BB, 256 thr.
// ---------------------------------------------------------------------------
__global__ __launch_bounds__(256) void k_qprep(
    const float* __restrict__ emb,
    const float* __restrict__ Wf,     // [128,128]
    const float* __restrict__ Ws,     // [256,128]
    const float* __restrict__ Wn,     // [128,384]
    const int*   __restrict__ fidx,
    const int*   __restrict__ lidx)
{
    __shared__ float ge[D], ef[D], el[D];
    __shared__ float qpart[2][D];
    __shared__ float qv[D];

    const int b   = blockIdx.x;
    const int tid = threadIdx.x;
    const float* E = emb + (size_t)b * NN * D;

    if (tid < D) {
        float sgm = 0.f;
        #pragma unroll
        for (int p = 0; p < SPM; ++p) sgm += g_msum[(size_t)(b * SPM + p) * D + tid];
        ge[tid] = sgm * (1.0f / NN);
        const int fi = fidx[b], li = lidx[b];
        ef[tid] = E[(size_t)fi * D + tid];
        el[tid] = E[(size_t)li * D + tid];
    }
    __syncthreads();

    {
        const int j = tid & 127;
        float a = 0.f;
        if (tid < D) {
            #pragma unroll 4
            for (int k = 0; k < D; ++k) a += ge[k] * Wf[k * D + j];
            qpart[0][j] = a;
        } else {
            #pragma unroll 4
            for (int k = 0; k < D; ++k) a += ef[k] * Ws[k * D + j];
            #pragma unroll 4
            for (int k = 0; k < D; ++k) a += el[k] * Ws[(D + k) * D + j];
            qpart[1][j] = a;
        }
    }
    __syncthreads();
    if (tid < D) qv[tid] = qpart[0][tid] + qpart[1][tid];
    __syncthreads();

    if (tid < D) {
        const float* wr = Wn + (size_t)tid * (3 * D);
        #pragma unroll
        for (int h = 0; h < H; ++h) {
            float a = 0.f;
            #pragma unroll
            for (int d4 = 0; d4 < 4; ++d4) {
                float4 w4 = *(const float4*)(wr + h * 16 + d4 * 4);
                a += qv[h * 16 + d4 * 4 + 0] * w4.x;
                a += qv[h * 16 + d4 * 4 + 1] * w4.y;
                a += qv[h * 16 + d4 * 4 + 2] * w4.z;
                a += qv[h * 16 + d4 * 4 + 3] * w4.w;
            }
            g_qkh[((size_t)b * H + h) * D + tid] = a;
        }
    }
}

// ---------------------------------------------------------------------------
// Kernel 2a: register-resident flash glimpse. grid = BB*SPG, 256 thr.
// Warp w handles rows r0+w, r0+w+8, ...  Lane owns 4 columns.
// Q (8 heads x 4 cols) + agg (8 heads x 4 cols) + (m,s) all in registers.
// Masked rows are skipped entirely (no load, no compute).
// In-CTA merge of the 8 warps' flash partials -> one SPG partial.
// ---------------------------------------------------------------------------
__global__ __launch_bounds__(256, 2) void k_glimpse_part(
    const float* __restrict__ emb,
    const void*  __restrict__ mask)
{
    __shared__ unsigned char sh_mk[RPG];
    __shared__ float sm_m[8][H];
    __shared__ float sm_s[8][H];
    __shared__ float sm_agg[8][H][D];   // 32 KB
    __shared__ float sm_e[8][H];
    __shared__ float gM[H];

    const int bx   = blockIdx.x;
    const int b    = bx / SPG, c = bx % SPG;
    const int tid  = threadIdx.x;
    const int wid  = tid >> 5;
    const int lane = tid & 31;
    const float* E = emb + (size_t)b * NN * D;
    const int mint = g_mask_is_int;
    const int r0 = c * RPG;

    // slice mask -> smem
    for (int i = tid; i < RPG; i += 256)
        sh_mk[i] = mask_at(mask, b * NN + r0 + i, mint) ? 1 : 0;

    // Q into registers: q[h] = qkh[b][h][lane*4 .. +4]
    float4 q[H];
    #pragma unroll
    for (int h = 0; h < H; ++h)
        q[h] = *(const float4*)&g_qkh[((size_t)b * H + h) * D + lane * 4];

    float m[H], s[H];
    float4 agg[H];
    #pragma unroll
    for (int h = 0; h < H; ++h) {
        m[h] = -3.0e38f; s[h] = 0.f;
        agg[h] = make_float4(0.f, 0.f, 0.f, 0.f);
    }
    __syncthreads();   // sh_mk ready

    int r = wid;                      // row offset within slice
    bool v0 = (r < RPG);
    bool v1 = (r + 8 < RPG);
    bool mc = v0 ? (sh_mk[r] != 0) : true;
    bool mn = v1 ? (sh_mk[r + 8] != 0) : true;
    float4 ec = (v0 && !mc) ? *(const float4*)(E + (size_t)(r0 + r) * D + lane * 4)
                            : make_float4(0.f, 0.f, 0.f, 0.f);

    while (v0) {
        // prefetch next row's data (predicated on its mask)
        const bool v2 = (r + 16 < RPG);
        const bool m2 = v2 ? (sh_mk[r + 16] != 0) : true;
        float4 en = (v1 && !mn)
            ? *(const float4*)(E + (size_t)(r0 + r + 8) * D + lane * 4)
            : make_float4(0.f, 0.f, 0.f, 0.f);

        if (!mc) {
            // 8 per-head partial dots (lane's 4 columns)
            float p[H];
            #pragma unroll
            for (int h = 0; h < H; ++h)
                p[h] = ec.x * q[h].x + ec.y * q[h].y + ec.z * q[h].z + ec.w * q[h].w;

            // split-butterfly reduce: 8 values over 32 lanes (9 shuffles)
            #pragma unroll
            for (int i = 0; i < 4; ++i) {           // offset 16: 8 -> 4
                float send = (lane & 16) ? p[i] : p[i + 4];
                float recv = __shfl_xor_sync(0xffffffffu, send, 16);
                p[i] = ((lane & 16) ? p[i + 4] : p[i]) + recv;
            }
            #pragma unroll
            for (int i = 0; i < 2; ++i) {           // offset 8: 4 -> 2
                float send = (lane & 8) ? p[i] : p[i + 2];
                float recv = __shfl_xor_sync(0xffffffffu, send, 8);
                p[i] = ((lane & 8) ? p[i + 2] : p[i]) + recv;
            }
            {                                        // offset 4: 2 -> 1
                float send = (lane & 4) ? p[0] : p[1];
                float recv = __shfl_xor_sync(0xffffffffu, send, 4);
                p[0] = ((lane & 4) ? p[1] : p[0]) + recv;
            }
            p[0] += __shfl_xor_sync(0xffffffffu, p[0], 2);
            p[0] += __shfl_xor_sync(0xffffffffu, p[0], 1);
            // lane holds full dot for head ((lane>>2)&7); head h lives on lane 4h

            float cf[H];
            #pragma unroll
            for (int h = 0; h < H; ++h)
                cf[h] = __shfl_sync(0xffffffffu, p[0], h << 2) * 0.25f; // 1/sqrt(16)

            // redundant per-lane flash state update (warp-uniform)
            bool anynew = false;
            #pragma unroll
            for (int h = 0; h < H; ++h) anynew = anynew || (cf[h] > m[h]);
            if (anynew) {   // rare
                #pragma unroll
                for (int h = 0; h < H; ++h) {
                    const float mnu = fmaxf(m[h], cf[h]);
                    const float cr  = __expf(m[h] - mnu);
                    m[h] = mnu; s[h] *= cr;
                    agg[h].x *= cr; agg[h].y *= cr; agg[h].z *= cr; agg[h].w *= cr;
                }
            }
            #pragma unroll
            for (int h = 0; h < H; ++h) {
                const float w = __expf(cf[h] - m[h]);
                s[h] += w;
                agg[h].x += w * ec.x; agg[h].y += w * ec.y;
                agg[h].z += w * ec.z; agg[h].w += w * ec.w;
            }
        }

        ec = en; mc = mn; mn = m2; v0 = v1; v1 = v2; r += 8;
    }

    // ---- in-CTA merge of 8 per-warp flash partials ----
    if (lane == 0) {
        #pragma unroll
        for (int h = 0; h < H; ++h) { sm_m[wid][h] = m[h]; sm_s[wid][h] = s[h]; }
    }
    #pragma unroll
    for (int h = 0; h < H; ++h)
        *(float4*)&sm_agg[wid][h][lane * 4] = agg[h];
    __syncthreads();

    if (tid < H) {
        float M = sm_m[0][tid];
        #pragma unroll
        for (int w = 1; w < 8; ++w) M = fmaxf(M, sm_m[w][tid]);
        gM[tid] = M;
    }
    __syncthreads();
    if (tid < 64) {
        const int w = tid >> 3, h = tid & 7;
        sm_e[w][h] = __expf(sm_m[w][h] - gM[h]);
    }
    __syncthreads();
    if (tid < H) {
        float S = 0.f;
        #pragma unroll
        for (int w = 0; w < 8; ++w) S += sm_s[w][tid] * sm_e[w][tid];
        g_gm[bx * H + tid] = gM[tid];
        g_gs[bx * H + tid] = S;
    }
    {
        const int h = tid >> 5, c4 = tid & 31;
        float4 a = make_float4(0.f, 0.f, 0.f, 0.f);
        #pragma unroll
        for (int w = 0; w < 8; ++w) {
            const float f = sm_e[w][h];
            float4 v = *(const float4*)&sm_agg[w][h][c4 * 4];
            a.x += f * v.x; a.y += f * v.y; a.z += f * v.z; a.w += f * v.w;
        }
        *(float4*)&g_gagg[((size_t)bx * H + h) * D + c4 * 4] = a;
    }
}

// ---------------------------------------------------------------------------
// Kernel 2b: merge SPG glimpse partials + epilogue. grid = BB, 128 threads.
// ---------------------------------------------------------------------------
__global__ __launch_bounds__(128) void k_gmerge(
    const float* __restrict__ Wn,
    const float* __restrict__ Wo)
{
    __shared__ float Ms[H], Ss[H], e_s[SPG][H];
    __shared__ float aggs[H * D];
    __shared__ float heads_s[D];
    __shared__ float glimpse_s[D];

    const int b = blockIdx.x, tid = threadIdx.x;

    if (tid < H) {
        float M = -3.0e38f;
        #pragma unroll
        for (int c = 0; c < SPG; ++c) M = fmaxf(M, g_gm[(b * SPG + c) * H + tid]);
        Ms[tid] = M;
    }
    __syncthreads();
    if (tid < SPG * H) {
        const int c = tid >> 3, h = tid & 7;
        e_s[c][h] = __expf(g_gm[(b * SPG + c) * H + h] - Ms[h]);
    }
    __syncthreads();
    if (tid < H) {
        float S = 0.f;
        #pragma unroll
        for (int c = 0; c < SPG; ++c) S += g_gs[(b * SPG + c) * H + tid] * e_s[c][tid];
        Ss[tid] = S;
    }
    __syncthreads();

    #pragma unroll
    for (int h = 0; h < H; ++h) {
        float a = 0.f;
        #pragma unroll
        for (int c = 0; c < SPG; ++c)
            a += g_gagg[((size_t)(b * SPG + c) * H + h) * D + tid] * e_s[c][h];
        aggs[h * D + tid] = a / Ss[h];
    }
    __syncthreads();

    {
        const int h = tid >> 4;
        const float* as = &aggs[h * D];
        float a = 0.f;
        #pragma unroll 4
        for (int j = 0; j < D; ++j) a += as[j] * Wn[(size_t)j * (3 * D) + D + tid];
        heads_s[tid] = a;
    }
    __syncthreads();

    {
        float a = 0.f;
        #pragma unroll 4
        for (int k = 0; k < D; ++k) a += heads_s[k] * Wo[k * D + tid];
        glimpse_s[tid] = a;
    }
    __syncthreads();

    {
        const float* wr = Wn + (size_t)tid * (3 * D) + 2 * D;
        float a = 0.f;
        #pragma unroll
        for (int dd = 0; dd < D; dd += 4) {
            float4 w4 = *(const float4*)(wr + dd);
            a += glimpse_s[dd + 0] * w4.x + glimpse_s[dd + 1] * w4.y
               + glimpse_s[dd + 2] * w4.z + glimpse_s[dd + 3] * w4.w;
        }
        g_gk[(size_t)b * D + tid] = a * 0.08838834764831845f;  // 1/sqrt(128)
    }
}

// ---------------------------------------------------------------------------
// Kernel 3a: logits slices, mask-predicated loads. grid = BB*SPL, 256 thr.
// ---------------------------------------------------------------------------
__global__ __launch_bounds__(256) void k_logits_part(
    const float* __restrict__ emb,
    const void*  __restrict__ mask,
    float*       __restrict__ out)
{
    __shared__ float gk_s[D];
    __shared__ unsigned char sh_mk[RPL];
    __shared__ float lg[RPL];
    __shared__ float red[256];

    const int bx   = blockIdx.x;
    const int b    = bx / SPL, c = bx % SPL;
    const int tid  = threadIdx.x;
    const int wid  = tid >> 5;
    const int lane = tid & 31;
    const int base = c * RPL;
    const float* E = emb + (size_t)b * NN * D;
    const int mint = g_mask_is_int;

    if (tid < D) gk_s[tid] = g_gk[(size_t)b * D + tid];
    for (int i = tid; i < RPL; i += 256)
        sh_mk[i] = mask_at(mask, b * NN + base + i, mint) ? 1 : 0;
    __syncthreads();
    const float4 g4 = *(const float4*)&gk_s[lane * 4];

    float wmax = -3.0e38f;
    for (int k = wid; k < RPL; k += 16) {
        const int  k2   = k + 8;
        const bool has2 = (k2 < RPL);
        const bool m1 = (sh_mk[k] != 0);
        const bool m2 = has2 ? (sh_mk[k2] != 0) : true;
        float4 e1 = (!m1) ? *(const float4*)(E + (size_t)(base + k) * D + lane * 4)
                          : make_float4(0.f, 0.f, 0.f, 0.f);
        float4 e2 = (!m2) ? *(const float4*)(E + (size_t)(base + k2) * D + lane * 4)
                          : make_float4(0.f, 0.f, 0.f, 0.f);
        float p1 = e1.x * g4.x + e1.y * g4.y + e1.z * g4.z + e1.w * g4.w;
        float p2 = e2.x * g4.x + e2.y * g4.y + e2.z * g4.z + e2.w * g4.w;
        #pragma unroll
        for (int o = 16; o; o >>= 1) {
            p1 += __shfl_xor_sync(0xffffffffu, p1, o);
            p2 += __shfl_xor_sync(0xffffffffu, p2, o);
        }
        float v1 = m1 ? NEGV : tanhf(p1) * 10.0f;
        wmax = fmaxf(wmax, v1);
        if (lane == 0) lg[k] = v1;
        if (has2) {
            float v2 = m2 ? NEGV : tanhf(p2) * 10.0f;
            wmax = fmaxf(wmax, v2);
            if (lane == 0) lg[k2] = v2;
        }
    }

    red[tid] = wmax;
    __syncthreads();
    #pragma unroll
    for (int st = 128; st > 0; st >>= 1) {
        if (tid < st) red[tid] = fmaxf(red[tid], red[tid + st]);
        __syncthreads();
    }
    const float M = red[0];
    __syncthreads();

    red[tid] = (tid < RPL) ? __expf(lg[tid] - M) : 0.f;   // RPL=250 <= 256
    __syncthreads();
    #pragma unroll
    for (int st = 128; st > 0; st >>= 1) {
        if (tid < st) red[tid] += red[tid + st];
        __syncthreads();
    }

    if (tid == 0) { g_lmax[bx] = M; g_lsum[bx] = red[0]; }
    for (int i = tid; i < RPL; i += 256) out[b * NN + base + i] = lg[i];
}

// ---------------------------------------------------------------------------
// Kernel 3b: fold slice (max, sum) into lse; subtract in-place. grid = BB.
// ---------------------------------------------------------------------------
__global__ __launch_bounds__(256) void k_fix(float* __restrict__ out)
{
    __shared__ float lse_s;
    const int b = blockIdx.x, tid = threadIdx.x;
    if (tid == 0) {
        float M = -3.0e38f;
        #pragma unroll
        for (int c = 0; c < SPL; ++c) M = fmaxf(M, g_lmax[b * SPL + c]);
        float S = 0.f;
        #pragma unroll
        for (int c = 0; c < SPL; ++c) S += g_lsum[b * SPL + c] * __expf(g_lmax[b * SPL + c] - M);
        lse_s = M + __logf(S);
    }
    __syncthreads();
    const float lse = lse_s;
    for (int i = tid; i < NN; i += 256) out[b * NN + i] -= lse;
}

// ---------------------------------------------------------------------------
// Launch. Inputs (metadata order): embeddings, W_node, W_fixed, W_step,
// W_out, first_idx, last_idx, mask. Output: float32 [256,1000].
// ---------------------------------------------------------------------------
extern "C" void kernel_launch(void* const* d_in, const int* in_sizes, int n_in,
                              void* d_out, int out_size)
{
    const float* emb  = (const float*)d_in[0];
    const float* Wn   = (const float*)d_in[1];
    const float* Wf   = (const float*)d_in[2];
    const float* Ws   = (const float*)d_in[3];
    const float* Wo   = (const float*)d_in[4];
    const int*   fi   = (const int*)d_in[5];
    const int*   li   = (const int*)d_in[6];
    const void*  mask = d_in[7];
    float*       out  = (float*)d_out;

    k_detect      <<<1, 256>>>((const unsigned int*)mask);
    k_mean_part   <<<BB * SPM, 256>>>(emb);
    k_qprep       <<<BB, 256>>>(emb, Wf, Ws, Wn, fi, li);
    k_glimpse_part<<<BB * SPG, 256>>>(emb, mask);
    k_gmerge      <<<BB, 128>>>(Wn, Wo);
    k_logits_part <<<BB * SPL, 256>>>(emb, mask, out);
    k_fix         <<<BB, 256>>>(out);
}

// round 10
// speedup vs baseline: 1.6012x; 1.1055x over previous
#include <cuda_runtime.h>
#include <cuda_bf16.h>

// Problem constants
#define BB   256
#define NN   1000
#define D    128
#define H    8
#define NEGV (-1e9f)

// Split factors
#define SPM  8            // mean split     -> grid 2048
#define SPG  8            // glimpse split  -> grid 2048
#define SPL  4            // logits split   -> grid 1024
#define RPM  (NN/SPM)     // 125 rows per mean CTA
#define RPG  (NN/SPG)     // 125 rows per glimpse CTA
#define RPL  (NN/SPL)     // 250 rows per logits CTA

#define CPAD 12           // compat row pitch (floats); 48B rows keep LDS.128 aligned

// Scratch (no allocs allowed)
__device__ float g_msum[BB * SPM * D];
__device__ float g_qkh [BB * H * D];
__device__ float g_gm  [BB * SPG * H];
__device__ float g_gs  [BB * SPG * H];
__device__ float g_gagg[BB * SPG * H * D];
__device__ float g_gk  [BB * D];
__device__ float g_lmax[BB * SPL];
__device__ float g_lsum[BB * SPL];
__device__ int   g_mask_is_int;

// ---------------------------------------------------------------------------
// Kernel 0: detect mask storage format (bool bytes vs int32). Deterministic.
// ---------------------------------------------------------------------------
__global__ void k_detect(const unsigned int* __restrict__ m) {
    __shared__ int bad;
    if (threadIdx.x == 0) bad = 0;
    __syncthreads();
    if (m[threadIdx.x] > 1u) bad = 1;
    __syncthreads();
    if (threadIdx.x == 0) g_mask_is_int = bad ? 0 : 1;
}

__device__ __forceinline__ bool mask_at(const void* m, int idx, int is_int) {
    if (is_int) return ((const int*)m)[idx] != 0;
    return ((const unsigned char*)m)[idx] != 0;
}

// ---------------------------------------------------------------------------
// Kernel 1a: mean partials. grid = BB*SPM.
// ---------------------------------------------------------------------------
__global__ __launch_bounds__(256) void k_mean_part(const float* __restrict__ emb)
{
    __shared__ float part[8][D];
    const int bx  = blockIdx.x;
    const int b   = bx / SPM, p = bx % SPM;
    const int tid = threadIdx.x;
    const int c4  = tid & 31, rg = tid >> 5;
    const float* E = emb + (size_t)b * NN * D;
    const int r0 = p * RPM, r1 = r0 + RPM;

    float4 acc = make_float4(0.f, 0.f, 0.f, 0.f);
    for (int r = r0 + rg; r < r1; r += 8) {
        float4 v = *(const float4*)(E + (size_t)r * D + c4 * 4);
        acc.x += v.x; acc.y += v.y; acc.z += v.z; acc.w += v.w;
    }
    ((float4*)part[rg])[c4] = acc;
    __syncthreads();

    if (tid < D) {
        float s = 0.f;
        #pragma unroll
        for (int g = 0; g < 8; ++g) s += part[g][tid];
        g_msum[(size_t)bx * D + tid] = s;
    }
}

// ---------------------------------------------------------------------------
// Kernel 1b: fold mean partials, compute q and qKh. grid = BB, 256 thr.
// ---------------------------------------------------------------------------
__global__ __launch_bounds__(256) void k_qprep(
    const float* __restrict__ emb,
    const float* __restrict__ Wf,     // [128,128]
    const float* __restrict__ Ws,     // [256,128]
    const float* __restrict__ Wn,     // [128,384]
    const int*   __restrict__ fidx,
    const int*   __restrict__ lidx)
{
    __shared__ float ge[D], ef[D], el[D];
    __shared__ float qpart[2][D];
    __shared__ float qv[D];

    const int b   = blockIdx.x;
    const int tid = threadIdx.x;
    const float* E = emb + (size_t)b * NN * D;

    if (tid < D) {
        float sgm = 0.f;
        #pragma unroll
        for (int p = 0; p < SPM; ++p) sgm += g_msum[(size_t)(b * SPM + p) * D + tid];
        ge[tid] = sgm * (1.0f / NN);
        const int fi = fidx[b], li = lidx[b];
        ef[tid] = E[(size_t)fi * D + tid];
        el[tid] = E[(size_t)li * D + tid];
    }
    __syncthreads();

    {
        const int j = tid & 127;
        float a = 0.f;
        if (tid < D) {
            #pragma unroll 4
            for (int k = 0; k < D; ++k) a += ge[k] * Wf[k * D + j];
            qpart[0][j] = a;
        } else {
            #pragma unroll 4
            for (int k = 0; k < D; ++k) a += ef[k] * Ws[k * D + j];
            #pragma unroll 4
            for (int k = 0; k < D; ++k) a += el[k] * Ws[(D + k) * D + j];
            qpart[1][j] = a;
        }
    }
    __syncthreads();
    if (tid < D) qv[tid] = qpart[0][tid] + qpart[1][tid];
    __syncthreads();

    if (tid < D) {
        const float* wr = Wn + (size_t)tid * (3 * D);
        #pragma unroll
        for (int h = 0; h < H; ++h) {
            float a = 0.f;
            #pragma unroll
            for (int d4 = 0; d4 < 4; ++d4) {
                float4 w4 = *(const float4*)(wr + h * 16 + d4 * 4);
                a += qv[h * 16 + d4 * 4 + 0] * w4.x;
                a += qv[h * 16 + d4 * 4 + 1] * w4.y;
                a += qv[h * 16 + d4 * 4 + 2] * w4.z;
                a += qv[h * 16 + d4 * 4 + 3] * w4.w;
            }
            g_qkh[((size_t)b * H + h) * D + tid] = a;
        }
    }
}

// ---------------------------------------------------------------------------
// Kernel 2a: two-pass flash glimpse slice. grid = BB*SPG, 256 thr.
//  Pass 1: compat[r][h] via register dots + 16-value split-butterfly
//          (2 rows per iteration, no exp, no agg regs).
//  Middle: warp-per-head batch softmax over the slice (max, exp, sum).
//  Pass 2: agg[h] += w[r][h] * E[r] with E re-read (L2-hot) and weights
//          read via 2 broadcast LDS.128 per row.
//  Merge 8 per-warp agg partials -> g_gagg; g_gm/g_gs from middle phase.
// ---------------------------------------------------------------------------
__global__ __launch_bounds__(256, 3) void k_glimpse_part(
    const float* __restrict__ emb,
    const void*  __restrict__ mask)
{
    __shared__ __align__(16) float sm_cp[RPG * CPAD];    // compat / weights
    __shared__ __align__(16) float sm_agg[8][H][D];      // 32 KB
    __shared__ unsigned char sh_mk[RPG];

    const int bx   = blockIdx.x;
    const int b    = bx / SPG, c = bx % SPG;
    const int tid  = threadIdx.x;
    const int wid  = tid >> 5;
    const int lane = tid & 31;
    const float* E = emb + (size_t)b * NN * D;
    const int mint = g_mask_is_int;
    const int r0 = c * RPG;

    // mask + compat init
    for (int i = tid; i < RPG; i += 256)
        sh_mk[i] = mask_at(mask, b * NN + r0 + i, mint) ? 1 : 0;
    for (int i = tid; i < RPG * CPAD; i += 256) sm_cp[i] = NEGV;

    // Q into registers: q[h] = qkh[b][h][lane*4 .. +4]
    float4 q[H];
    #pragma unroll
    for (int h = 0; h < H; ++h)
        q[h] = *(const float4*)&g_qkh[((size_t)b * H + h) * D + lane * 4];
    __syncthreads();

    // ---- Pass 1: compat ----
    // warp w owns rows == w (mod 8); iteration handles pair (r, r+8)
    for (int r = wid; r < RPG; r += 16) {
        const int  rb = r + 8;
        const bool vb = (rb < RPG);
        const bool m0 = (sh_mk[r] != 0);
        const bool m1 = vb ? (sh_mk[rb] != 0) : true;
        if (m0 && m1) continue;

        float4 e0 = (!m0) ? *(const float4*)(E + (size_t)(r0 + r) * D + lane * 4)
                          : make_float4(0.f, 0.f, 0.f, 0.f);
        float4 e1 = (vb && !m1) ? *(const float4*)(E + (size_t)(r0 + rb) * D + lane * 4)
                                : make_float4(0.f, 0.f, 0.f, 0.f);

        float p[16];
        #pragma unroll
        for (int h = 0; h < H; ++h) {
            p[h]     = e0.x * q[h].x + e0.y * q[h].y + e0.z * q[h].z + e0.w * q[h].w;
            p[8 + h] = e1.x * q[h].x + e1.y * q[h].y + e1.z * q[h].z + e1.w * q[h].w;
        }

        // split-butterfly: 16 sums over 32 lanes in 16 shuffles.
        // value index bits: 8*b16 + 4*b8 + 2*b4 + 1*b2 of the lane id.
        #pragma unroll
        for (int i = 0; i < 8; ++i) {
            float send = (lane & 16) ? p[i] : p[i + 8];
            float recv = __shfl_xor_sync(0xffffffffu, send, 16);
            p[i] = ((lane & 16) ? p[i + 8] : p[i]) + recv;
        }
        #pragma unroll
        for (int i = 0; i < 4; ++i) {
            float send = (lane & 8) ? p[i] : p[i + 4];
            float recv = __shfl_xor_sync(0xffffffffu, send, 8);
            p[i] = ((lane & 8) ? p[i + 4] : p[i]) + recv;
        }
        #pragma unroll
        for (int i = 0; i < 2; ++i) {
            float send = (lane & 4) ? p[i] : p[i + 2];
            float recv = __shfl_xor_sync(0xffffffffu, send, 4);
            p[i] = ((lane & 4) ? p[i + 2] : p[i]) + recv;
        }
        {
            float send = (lane & 2) ? p[0] : p[1];
            float recv = __shfl_xor_sync(0xffffffffu, send, 2);
            p[0] = ((lane & 2) ? p[1] : p[0]) + recv;
        }
        p[0] += __shfl_xor_sync(0xffffffffu, p[0], 1);

        // lane l holds sum of value v=(l>>1)&15 : row j = v>>3, head = v&7
        if ((lane & 1) == 0) {
            const int v = (lane >> 1) & 15;
            const int j = v >> 3, h = v & 7;
            const bool ok = j ? (vb && !m1) : (!m0);
            if (ok) sm_cp[(r + 8 * j) * CPAD + h] = p[0] * 0.25f;  // 1/sqrt(16)
        }
    }
    __syncthreads();

    // ---- Middle: per-head softmax over the slice (warp h) ----
    {
        const int h = wid;
        float mx = -3.0e38f;
        for (int r = lane; r < RPG; r += 32) mx = fmaxf(mx, sm_cp[r * CPAD + h]);
        #pragma unroll
        for (int o = 16; o; o >>= 1) mx = fmaxf(mx, __shfl_xor_sync(0xffffffffu, mx, o));
        float sum = 0.f;
        for (int r = lane; r < RPG; r += 32) {
            const float w = __expf(sm_cp[r * CPAD + h] - mx);
            sm_cp[r * CPAD + h] = w;
            sum += w;
        }
        #pragma unroll
        for (int o = 16; o; o >>= 1) sum += __shfl_xor_sync(0xffffffffu, sum, o);
        if (lane == 0) { g_gm[bx * H + h] = mx; g_gs[bx * H + h] = sum; }
    }
    __syncthreads();

    // ---- Pass 2: weighted aggregate (Q regs dead; agg regs live) ----
    float4 agg[H];
    #pragma unroll
    for (int h = 0; h < H; ++h) agg[h] = make_float4(0.f, 0.f, 0.f, 0.f);

    for (int r = wid; r < RPG; r += 16) {
        const int  rb = r + 8;
        const bool vb = (rb < RPG);
        const bool m0 = (sh_mk[r] != 0);
        const bool m1 = vb ? (sh_mk[rb] != 0) : true;

        if (!m0) {
            float4 e0 = *(const float4*)(E + (size_t)(r0 + r) * D + lane * 4);
            float4 wa = *(const float4*)&sm_cp[r * CPAD];      // broadcast LDS.128
            float4 wb = *(const float4*)&sm_cp[r * CPAD + 4];
            const float w[8] = {wa.x, wa.y, wa.z, wa.w, wb.x, wb.y, wb.z, wb.w};
            #pragma unroll
            for (int h = 0; h < H; ++h) {
                agg[h].x += w[h] * e0.x; agg[h].y += w[h] * e0.y;
                agg[h].z += w[h] * e0.z; agg[h].w += w[h] * e0.w;
            }
        }
        if (!m1) {
            float4 e1 = *(const float4*)(E + (size_t)(r0 + rb) * D + lane * 4);
            float4 wa = *(const float4*)&sm_cp[rb * CPAD];
            float4 wb = *(const float4*)&sm_cp[rb * CPAD + 4];
            const float w[8] = {wa.x, wa.y, wa.z, wa.w, wb.x, wb.y, wb.z, wb.w};
            #pragma unroll
            for (int h = 0; h < H; ++h) {
                agg[h].x += w[h] * e1.x; agg[h].y += w[h] * e1.y;
                agg[h].z += w[h] * e1.z; agg[h].w += w[h] * e1.w;
            }
        }
    }

    // ---- merge 8 per-warp agg partials (plain sum; weights already exp'd) ----
    #pragma unroll
    for (int h = 0; h < H; ++h)
        *(float4*)&sm_agg[wid][h][lane * 4] = agg[h];
    __syncthreads();

    {
        const int h = tid >> 5, c4 = tid & 31;
        float4 a = make_float4(0.f, 0.f, 0.f, 0.f);
        #pragma unroll
        for (int w = 0; w < 8; ++w) {
            float4 v = *(const float4*)&sm_agg[w][h][c4 * 4];
            a.x += v.x; a.y += v.y; a.z += v.z; a.w += v.w;
        }
        *(float4*)&g_gagg[((size_t)bx * H + h) * D + c4 * 4] = a;
    }
}

// ---------------------------------------------------------------------------
// Kernel 2b: merge SPG glimpse partials + epilogue. grid = BB, 128 threads.
// ---------------------------------------------------------------------------
__global__ __launch_bounds__(128) void k_gmerge(
    const float* __restrict__ Wn,
    const float* __restrict__ Wo)
{
    __shared__ float Ms[H], Ss[H], e_s[SPG][H];
    __shared__ float aggs[H * D];
    __shared__ float heads_s[D];
    __shared__ float glimpse_s[D];

    const int b = blockIdx.x, tid = threadIdx.x;

    if (tid < H) {
        float M = -3.0e38f;
        #pragma unroll
        for (int c = 0; c < SPG; ++c) M = fmaxf(M, g_gm[(b * SPG + c) * H + tid]);
        Ms[tid] = M;
    }
    __syncthreads();
    if (tid < SPG * H) {
        const int c = tid >> 3, h = tid & 7;
        e_s[c][h] = __expf(g_gm[(b * SPG + c) * H + h] - Ms[h]);
    }
    __syncthreads();
    if (tid < H) {
        float S = 0.f;
        #pragma unroll
        for (int c = 0; c < SPG; ++c) S += g_gs[(b * SPG + c) * H + tid] * e_s[c][tid];
        Ss[tid] = S;
    }
    __syncthreads();

    #pragma unroll
    for (int h = 0; h < H; ++h) {
        float a = 0.f;
        #pragma unroll
        for (int c = 0; c < SPG; ++c)
            a += g_gagg[((size_t)(b * SPG + c) * H + h) * D + tid] * e_s[c][h];
        aggs[h * D + tid] = a / Ss[h];
    }
    __syncthreads();

    {
        const int h = tid >> 4;
        const float* as = &aggs[h * D];
        float a = 0.f;
        #pragma unroll 4
        for (int j = 0; j < D; ++j) a += as[j] * Wn[(size_t)j * (3 * D) + D + tid];
        heads_s[tid] = a;
    }
    __syncthreads();

    {
        float a = 0.f;
        #pragma unroll 4
        for (int k = 0; k < D; ++k) a += heads_s[k] * Wo[k * D + tid];
        glimpse_s[tid] = a;
    }
    __syncthreads();

    {
        const float* wr = Wn + (size_t)tid * (3 * D) + 2 * D;
        float a = 0.f;
        #pragma unroll
        for (int dd = 0; dd < D; dd += 4) {
            float4 w4 = *(const float4*)(wr + dd);
            a += glimpse_s[dd + 0] * w4.x + glimpse_s[dd + 1] * w4.y
               + glimpse_s[dd + 2] * w4.z + glimpse_s[dd + 3] * w4.w;
        }
        g_gk[(size_t)b * D + tid] = a * 0.08838834764831845f;  // 1/sqrt(128)
    }
}

// ---------------------------------------------------------------------------
// Kernel 3a: logits slices. grid = BB*SPL, 256 thr. 4 rows per warp-iter
// via 4-value split-butterfly (6 shuffles / 4 rows), mask-predicated loads.
// ---------------------------------------------------------------------------
__global__ __launch_bounds__(256) void k_logits_part(
    const float* __restrict__ emb,
    const void*  __restrict__ mask,
    float*       __restrict__ out)
{
    __shared__ float gk_s[D];
    __shared__ unsigned char sh_mk[RPL];
    __shared__ float lg[RPL];
    __shared__ float red[256];

    const int bx   = blockIdx.x;
    const int b    = bx / SPL, c = bx % SPL;
    const int tid  = threadIdx.x;
    const int wid  = tid >> 5;
    const int lane = tid & 31;
    const int base = c * RPL;
    const float* E = emb + (size_t)b * NN * D;
    const int mint = g_mask_is_int;

    if (tid < D) gk_s[tid] = g_gk[(size_t)b * D + tid];
    for (int i = tid; i < RPL; i += 256)
        sh_mk[i] = mask_at(mask, b * NN + base + i, mint) ? 1 : 0;
    __syncthreads();
    const float4 g4 = *(const float4*)&gk_s[lane * 4];

    float wmax = -3.0e38f;
    #pragma unroll 1
    for (int it = 0; it < (RPL + 31) / 32; ++it) {
        const int r = wid * 4 + it * 32;      // rows r .. r+3
        const bool va0 = (r     < RPL), va1 = (r + 1 < RPL);
        const bool va2 = (r + 2 < RPL), va3 = (r + 3 < RPL);
        const bool m0 = va0 ? (sh_mk[r]     != 0) : true;
        const bool m1 = va1 ? (sh_mk[r + 1] != 0) : true;
        const bool m2 = va2 ? (sh_mk[r + 2] != 0) : true;
        const bool m3 = va3 ? (sh_mk[r + 3] != 0) : true;

        float4 z = make_float4(0.f, 0.f, 0.f, 0.f);
        float4 e0 = (!m0) ? *(const float4*)(E + (size_t)(base + r    ) * D + lane * 4) : z;
        float4 e1 = (!m1) ? *(const float4*)(E + (size_t)(base + r + 1) * D + lane * 4) : z;
        float4 e2 = (!m2) ? *(const float4*)(E + (size_t)(base + r + 2) * D + lane * 4) : z;
        float4 e3 = (!m3) ? *(const float4*)(E + (size_t)(base + r + 3) * D + lane * 4) : z;

        float p[4];
        p[0] = e0.x * g4.x + e0.y * g4.y + e0.z * g4.z + e0.w * g4.w;
        p[1] = e1.x * g4.x + e1.y * g4.y + e1.z * g4.z + e1.w * g4.w;
        p[2] = e2.x * g4.x + e2.y * g4.y + e2.z * g4.z + e2.w * g4.w;
        p[3] = e3.x * g4.x + e3.y * g4.y + e3.z * g4.z + e3.w * g4.w;

        // 4 sums over 32 lanes in 6 shuffles; value v = 2*b16 + b8 of lane.
        #pragma unroll
        for (int i = 0; i < 2; ++i) {
            float send = (lane & 16) ? p[i] : p[i + 2];
            float recv = __shfl_xor_sync(0xffffffffu, send, 16);
            p[i] = ((lane & 16) ? p[i + 2] : p[i]) + recv;
        }
        {
            float send = (lane & 8) ? p[0] : p[1];
            float recv = __shfl_xor_sync(0xffffffffu, send, 8);
            p[0] = ((lane & 8) ? p[1] : p[0]) + recv;
        }
        p[0] += __shfl_xor_sync(0xffffffffu, p[0], 4);
        p[0] += __shfl_xor_sync(0xffffffffu, p[0], 2);
        p[0] += __shfl_xor_sync(0xffffffffu, p[0], 1);

        const int v   = ((lane & 16) ? 2 : 0) | ((lane & 8) ? 1 : 0);
        const int row = r + v;
        if (row < RPL) {
            const bool mm = (sh_mk[row] != 0);
            const float val = mm ? NEGV : tanhf(p[0]) * 10.0f;
            wmax = fmaxf(wmax, val);
            if ((lane & 7) == 0) lg[row] = val;
        }
    }

    red[tid] = wmax;
    __syncthreads();
    #pragma unroll
    for (int st = 128; st > 0; st >>= 1) {
        if (tid < st) red[tid] = fmaxf(red[tid], red[tid + st]);
        __syncthreads();
    }
    const float M = red[0];
    __syncthreads();

    red[tid] = (tid < RPL) ? __expf(lg[tid] - M) : 0.f;   // RPL=250 <= 256
    __syncthreads();
    #pragma unroll
    for (int st = 128; st > 0; st >>= 1) {
        if (tid < st) red[tid] += red[tid + st];
        __syncthreads();
    }

    if (tid == 0) { g_lmax[bx] = M; g_lsum[bx] = red[0]; }
    for (int i = tid; i < RPL; i += 256) out[b * NN + base + i] = lg[i];
}

// ---------------------------------------------------------------------------
// Kernel 3b: fold slice (max, sum) into lse; subtract in-place. grid = BB.
// ---------------------------------------------------------------------------
__global__ __launch_bounds__(256) void k_fix(float* __restrict__ out)
{
    __shared__ float lse_s;
    const int b = blockIdx.x, tid = threadIdx.x;
    if (tid == 0) {
        float M = -3.0e38f;
        #pragma unroll
        for (int c = 0; c < SPL; ++c) M = fmaxf(M, g_lmax[b * SPL + c]);
        float S = 0.f;
        #pragma unroll
        for (int c = 0; c < SPL; ++c) S += g_lsum[b * SPL + c] * __expf(g_lmax[b * SPL + c] - M);
        lse_s = M + __logf(S);
    }
    __syncthreads();
    const float lse = lse_s;
    for (int i = tid; i < NN; i += 256) out[b * NN + i] -= lse;
}

// ---------------------------------------------------------------------------
// Launch. Inputs (metadata order): embeddings, W_node, W_fixed, W_step,
// W_out, first_idx, last_idx, mask. Output: float32 [256,1000].
// ---------------------------------------------------------------------------
extern "C" void kernel_launch(void* const* d_in, const int* in_sizes, int n_in,
                              void* d_out, int out_size)
{
    const float* emb  = (const float*)d_in[0];
    const float* Wn   = (const float*)d_in[1];
    const float* Wf   = (const float*)d_in[2];
    const float* Ws   = (const float*)d_in[3];
    const float* Wo   = (const float*)d_in[4];
    const int*   fi   = (const int*)d_in[5];
    const int*   li   = (const int*)d_in[6];
    const void*  mask = d_in[7];
    float*       out  = (float*)d_out;

    k_detect      <<<1, 256>>>((const unsigned int*)mask);
    k_mean_part   <<<BB * SPM, 256>>>(emb);
    k_qprep       <<<BB, 256>>>(emb, Wf, Ws, Wn, fi, li);
    k_glimpse_part<<<BB * SPG, 256>>>(emb, mask);
    k_gmerge      <<<BB, 128>>>(Wn, Wo);
    k_logits_part <<<BB * SPL, 256>>>(emb, mask, out);
    k_fix         <<<BB, 256>>>(out);
}

// round 11
// speedup vs baseline: 1.6827x; 1.0509x over previous
#include <cuda_runtime.h>
#include <cuda_bf16.h>

// Problem constants
#define BB   256
#define NN   1000
#define D    128
#define H    8
#define NEGV (-1e9f)

// Split factors
#define SPM  8            // mean split     -> grid 2048
#define SPG  8            // glimpse split  -> grid 2048
#define SPL  8            // logits split   -> grid 2048
#define RPM  (NN/SPM)     // 125 rows per mean CTA
#define RPG  (NN/SPG)     // 125 rows per glimpse CTA
#define RPL  (NN/SPL)     // 125 rows per logits CTA

#define CPAD 12           // compat row pitch (floats); 48B rows keep LDS.128 aligned

// ---- packed f32x2 helpers (sm_103a) ----
__device__ __forceinline__ unsigned long long mul2_(unsigned long long a, unsigned long long b) {
    unsigned long long d; asm("mul.rn.f32x2 %0, %1, %2;" : "=l"(d) : "l"(a), "l"(b)); return d;
}
__device__ __forceinline__ unsigned long long fma2_(unsigned long long a, unsigned long long b, unsigned long long c) {
    unsigned long long d; asm("fma.rn.f32x2 %0, %1, %2, %3;" : "=l"(d) : "l"(a), "l"(b), "l"(c)); return d;
}
__device__ __forceinline__ unsigned long long add2_(unsigned long long a, unsigned long long b) {
    unsigned long long d; asm("add.rn.f32x2 %0, %1, %2;" : "=l"(d) : "l"(a), "l"(b)); return d;
}
__device__ __forceinline__ float lohi_(unsigned long long p) {
    unsigned int lo, hi; asm("mov.b64 {%0, %1}, %2;" : "=r"(lo), "=r"(hi) : "l"(p));
    return __uint_as_float(lo) + __uint_as_float(hi);
}
__device__ __forceinline__ unsigned long long bcast2_(float x) {
    unsigned long long d; asm("mov.b64 %0, {%1, %1};" : "=l"(d) : "f"(x)); return d;
}

// Scratch (no allocs allowed)
__device__ float g_msum[BB * SPM * D];
__device__ float g_qkh [BB * H * D];
__device__ float g_gm  [BB * SPG * H];
__device__ float g_gs  [BB * SPG * H];
__device__ float g_gagg[BB * SPG * H * D];
__device__ float g_gk  [BB * D];
__device__ float g_lmax[BB * SPL];
__device__ float g_lsum[BB * SPL];
__device__ int   g_mask_is_int;

__device__ __forceinline__ bool mask_at(const void* m, int idx, int is_int) {
    if (is_int) return ((const int*)m)[idx] != 0;
    return ((const unsigned char*)m)[idx] != 0;
}

// ---------------------------------------------------------------------------
// Kernel 1a: mean partials. grid = BB*SPM. Block 0 also resolves the mask
// storage format (bool bytes vs int32) — deterministic, data-driven.
// ---------------------------------------------------------------------------
__global__ __launch_bounds__(256) void k_mean_part(
    const float* __restrict__ emb,
    const unsigned int* __restrict__ mask_words)
{
    __shared__ float part[8][D];
    __shared__ int bad;
    const int bx  = blockIdx.x;
    const int b   = bx / SPM, p = bx % SPM;
    const int tid = threadIdx.x;
    const int c4  = tid & 31, rg = tid >> 5;
    const float* E = emb + (size_t)b * NN * D;
    const int r0 = p * RPM, r1 = r0 + RPM;

    if (bx == 0) {     // mask-format detect (first 256 LE words all in {0,1} => int32)
        if (tid == 0) bad = 0;
        __syncthreads();
        if (mask_words[tid] > 1u) bad = 1;
        __syncthreads();
        if (tid == 0) g_mask_is_int = bad ? 0 : 1;
    }

    float4 acc = make_float4(0.f, 0.f, 0.f, 0.f);
    for (int r = r0 + rg; r < r1; r += 8) {
        float4 v = *(const float4*)(E + (size_t)r * D + c4 * 4);
        acc.x += v.x; acc.y += v.y; acc.z += v.z; acc.w += v.w;
    }
    ((float4*)part[rg])[c4] = acc;
    __syncthreads();

    if (tid < D) {
        float s = 0.f;
        #pragma unroll
        for (int g = 0; g < 8; ++g) s += part[g][tid];
        g_msum[(size_t)bx * D + tid] = s;
    }
}

// ---------------------------------------------------------------------------
// Kernel 1b: fold mean partials, compute q and qKh. grid = BB, 256 thr.
// ---------------------------------------------------------------------------
__global__ __launch_bounds__(256) void k_qprep(
    const float* __restrict__ emb,
    const float* __restrict__ Wf,     // [128,128]
    const float* __restrict__ Ws,     // [256,128]
    const float* __restrict__ Wn,     // [128,384]
    const int*   __restrict__ fidx,
    const int*   __restrict__ lidx)
{
    __shared__ float ge[D], ef[D], el[D];
    __shared__ float qpart[2][D];
    __shared__ float qv[D];

    const int b   = blockIdx.x;
    const int tid = threadIdx.x;
    const float* E = emb + (size_t)b * NN * D;

    if (tid < D) {
        float sgm = 0.f;
        #pragma unroll
        for (int p = 0; p < SPM; ++p) sgm += g_msum[(size_t)(b * SPM + p) * D + tid];
        ge[tid] = sgm * (1.0f / NN);
        const int fi = fidx[b], li = lidx[b];
        ef[tid] = E[(size_t)fi * D + tid];
        el[tid] = E[(size_t)li * D + tid];
    }
    __syncthreads();

    {
        const int j = tid & 127;
        float a = 0.f;
        if (tid < D) {
            #pragma unroll 4
            for (int k = 0; k < D; ++k) a += ge[k] * Wf[k * D + j];
            qpart[0][j] = a;
        } else {
            #pragma unroll 4
            for (int k = 0; k < D; ++k) a += ef[k] * Ws[k * D + j];
            #pragma unroll 4
            for (int k = 0; k < D; ++k) a += el[k] * Ws[(D + k) * D + j];
            qpart[1][j] = a;
        }
    }
    __syncthreads();
    if (tid < D) qv[tid] = qpart[0][tid] + qpart[1][tid];
    __syncthreads();

    if (tid < D) {
        const float* wr = Wn + (size_t)tid * (3 * D);
        #pragma unroll
        for (int h = 0; h < H; ++h) {
            float a = 0.f;
            #pragma unroll
            for (int d4 = 0; d4 < 4; ++d4) {
                float4 w4 = *(const float4*)(wr + h * 16 + d4 * 4);
                a += qv[h * 16 + d4 * 4 + 0] * w4.x;
                a += qv[h * 16 + d4 * 4 + 1] * w4.y;
                a += qv[h * 16 + d4 * 4 + 2] * w4.z;
                a += qv[h * 16 + d4 * 4 + 3] * w4.w;
            }
            g_qkh[((size_t)b * H + h) * D + tid] = a;
        }
    }
}

// ---------------------------------------------------------------------------
// Kernel 2a: two-pass flash glimpse slice, packed-f32x2 math.
//  Pass 1: compat via packed dots + 16-value split-butterfly.
//  Middle: warp-per-head softmax (mask-guarded; masked slots never touched).
//  Pass 2: packed-FMA aggregate, E re-read (L1/L2-hot), LDS.128 weights.
// ---------------------------------------------------------------------------
__global__ __launch_bounds__(256, 3) void k_glimpse_part(
    const float* __restrict__ emb,
    const void*  __restrict__ mask)
{
    __shared__ __align__(16) float sm_cp[RPG * CPAD];         // compat / weights
    __shared__ __align__(16) ulonglong2 sm_agg[8][H][32];     // 32 KB
    __shared__ unsigned char sh_mk[RPG];

    const int bx   = blockIdx.x;
    const int b    = bx / SPG, c = bx % SPG;
    const int tid  = threadIdx.x;
    const int wid  = tid >> 5;
    const int lane = tid & 31;
    const float* E = emb + (size_t)b * NN * D;
    const int mint = g_mask_is_int;
    const int r0 = c * RPG;

    for (int i = tid; i < RPG; i += 256)
        sh_mk[i] = mask_at(mask, b * NN + r0 + i, mint) ? 1 : 0;

    // Q into registers as packed pairs: q[h] = {cols 4l..4l+1, 4l+2..4l+3}
    ulonglong2 q[H];
    #pragma unroll
    for (int h = 0; h < H; ++h)
        q[h] = *(const ulonglong2*)&g_qkh[((size_t)b * H + h) * D + lane * 4];
    __syncthreads();

    // ---- Pass 1: compat ---- (warp w owns rows == w mod 8; pair (r, r+8))
    #pragma unroll
    for (int k = 0; k < 8; ++k) {
        const int  r  = wid + 16 * k;          // <= 119 < RPG always
        const int  rb = r + 8;
        const bool vb = (rb < RPG);
        const bool m0 = (sh_mk[r] != 0);
        const bool m1 = vb ? (sh_mk[rb] != 0) : true;
        if (m0 && m1) continue;

        ulonglong2 z2; z2.x = 0ull; z2.y = 0ull;
        ulonglong2 e0 = (!m0) ? *(const ulonglong2*)(E + (size_t)(r0 + r) * D + lane * 4) : z2;
        ulonglong2 e1 = (vb && !m1) ? *(const ulonglong2*)(E + (size_t)(r0 + rb) * D + lane * 4) : z2;

        float p[16];
        #pragma unroll
        for (int h = 0; h < H; ++h) {
            p[h]     = lohi_(fma2_(e0.y, q[h].y, mul2_(e0.x, q[h].x)));
            p[8 + h] = lohi_(fma2_(e1.y, q[h].y, mul2_(e1.x, q[h].x)));
        }

        // split-butterfly: 16 sums over 32 lanes in 16 shuffles.
        #pragma unroll
        for (int i = 0; i < 8; ++i) {
            float send = (lane & 16) ? p[i] : p[i + 8];
            float recv = __shfl_xor_sync(0xffffffffu, send, 16);
            p[i] = ((lane & 16) ? p[i + 8] : p[i]) + recv;
        }
        #pragma unroll
        for (int i = 0; i < 4; ++i) {
            float send = (lane & 8) ? p[i] : p[i + 4];
            float recv = __shfl_xor_sync(0xffffffffu, send, 8);
            p[i] = ((lane & 8) ? p[i + 4] : p[i]) + recv;
        }
        #pragma unroll
        for (int i = 0; i < 2; ++i) {
            float send = (lane & 4) ? p[i] : p[i + 2];
            float recv = __shfl_xor_sync(0xffffffffu, send, 4);
            p[i] = ((lane & 4) ? p[i + 2] : p[i]) + recv;
        }
        {
            float send = (lane & 2) ? p[0] : p[1];
            float recv = __shfl_xor_sync(0xffffffffu, send, 2);
            p[0] = ((lane & 2) ? p[1] : p[0]) + recv;
        }
        p[0] += __shfl_xor_sync(0xffffffffu, p[0], 1);

        // lane l holds value v=(l>>1)&15 : row j = v>>3, head = v&7
        if ((lane & 1) == 0) {
            const int v = (lane >> 1) & 15;
            const int j = v >> 3, h = v & 7;
            const bool ok = j ? (vb && !m1) : (!m0);
            if (ok) sm_cp[(r + 8 * j) * CPAD + h] = p[0] * 0.25f;  // 1/sqrt(16)
        }
    }
    __syncthreads();

    // ---- Middle: per-head softmax over the slice (warp = head). Masked
    //      slots are never read nor written (hold garbage harmlessly). ----
    {
        const int h = wid;
        float mx = -3.0e38f;
        for (int r = lane; r < RPG; r += 32)
            if (!sh_mk[r]) mx = fmaxf(mx, sm_cp[r * CPAD + h]);
        #pragma unroll
        for (int o = 16; o; o >>= 1) mx = fmaxf(mx, __shfl_xor_sync(0xffffffffu, mx, o));
        float sum = 0.f;
        for (int r = lane; r < RPG; r += 32)
            if (!sh_mk[r]) {
                const float w = __expf(sm_cp[r * CPAD + h] - mx);
                sm_cp[r * CPAD + h] = w;
                sum += w;
            }
        #pragma unroll
        for (int o = 16; o; o >>= 1) sum += __shfl_xor_sync(0xffffffffu, sum, o);
        if (lane == 0) { g_gm[bx * H + h] = mx; g_gs[bx * H + h] = sum; }
    }
    __syncthreads();

    // ---- Pass 2: packed weighted aggregate ----
    unsigned long long aggA[H], aggB[H];
    #pragma unroll
    for (int h = 0; h < H; ++h) { aggA[h] = 0ull; aggB[h] = 0ull; }

    #pragma unroll
    for (int k = 0; k < 8; ++k) {
        const int  r  = wid + 16 * k;
        const int  rb = r + 8;
        const bool vb = (rb < RPG);
        const bool m0 = (sh_mk[r] != 0);
        const bool m1 = vb ? (sh_mk[rb] != 0) : true;

        if (!m0) {
            ulonglong2 ev = *(const ulonglong2*)(E + (size_t)(r0 + r) * D + lane * 4);
            const float4 wa = *(const float4*)&sm_cp[r * CPAD];
            const float4 wb = *(const float4*)&sm_cp[r * CPAD + 4];
            const float wv[8] = {wa.x, wa.y, wa.z, wa.w, wb.x, wb.y, wb.z, wb.w};
            #pragma unroll
            for (int h = 0; h < H; ++h) {
                const unsigned long long ww = bcast2_(wv[h]);
                aggA[h] = fma2_(ww, ev.x, aggA[h]);
                aggB[h] = fma2_(ww, ev.y, aggB[h]);
            }
        }
        if (!m1) {
            ulonglong2 ev = *(const ulonglong2*)(E + (size_t)(r0 + rb) * D + lane * 4);
            const float4 wa = *(const float4*)&sm_cp[rb * CPAD];
            const float4 wb = *(const float4*)&sm_cp[rb * CPAD + 4];
            const float wv[8] = {wa.x, wa.y, wa.z, wa.w, wb.x, wb.y, wb.z, wb.w};
            #pragma unroll
            for (int h = 0; h < H; ++h) {
                const unsigned long long ww = bcast2_(wv[h]);
                aggA[h] = fma2_(ww, ev.x, aggA[h]);
                aggB[h] = fma2_(ww, ev.y, aggB[h]);
            }
        }
    }

    // ---- merge 8 per-warp agg partials (plain packed sums) ----
    #pragma unroll
    for (int h = 0; h < H; ++h) {
        ulonglong2 v; v.x = aggA[h]; v.y = aggB[h];
        sm_agg[wid][h][lane] = v;
    }
    __syncthreads();

    {
        const int h = tid >> 5, c4 = tid & 31;
        unsigned long long ax = 0ull, bx2 = 0ull;
        #pragma unroll
        for (int w = 0; w < 8; ++w) {
            ulonglong2 v = sm_agg[w][h][c4];
            ax = add2_(ax, v.x); bx2 = add2_(bx2, v.y);
        }
        ulonglong2 o; o.x = ax; o.y = bx2;
        *(ulonglong2*)&g_gagg[((size_t)bx * H + h) * D + c4 * 4] = o;
    }
}

// ---------------------------------------------------------------------------
// Kernel 2b: merge SPG glimpse partials + epilogue. grid = BB, 128 threads.
// ---------------------------------------------------------------------------
__global__ __launch_bounds__(128) void k_gmerge(
    const float* __restrict__ Wn,
    const float* __restrict__ Wo)
{
    __shared__ float Ms[H], Ss[H], e_s[SPG][H];
    __shared__ float aggs[H * D];
    __shared__ float heads_s[D];
    __shared__ float glimpse_s[D];

    const int b = blockIdx.x, tid = threadIdx.x;

    if (tid < H) {
        float M = -3.0e38f;
        #pragma unroll
        for (int c = 0; c < SPG; ++c) M = fmaxf(M, g_gm[(b * SPG + c) * H + tid]);
        Ms[tid] = M;
    }
    __syncthreads();
    if (tid < SPG * H) {
        const int c = tid >> 3, h = tid & 7;
        e_s[c][h] = __expf(g_gm[(b * SPG + c) * H + h] - Ms[h]);
    }
    __syncthreads();
    if (tid < H) {
        float S = 0.f;
        #pragma unroll
        for (int c = 0; c < SPG; ++c) S += g_gs[(b * SPG + c) * H + tid] * e_s[c][tid];
        Ss[tid] = S;
    }
    __syncthreads();

    #pragma unroll
    for (int h = 0; h < H; ++h) {
        float a = 0.f;
        #pragma unroll
        for (int c = 0; c < SPG; ++c)
            a += g_gagg[((size_t)(b * SPG + c) * H + h) * D + tid] * e_s[c][h];
        aggs[h * D + tid] = a / Ss[h];
    }
    __syncthreads();

    {
        const int h = tid >> 4;
        const float* as = &aggs[h * D];
        float a = 0.f;
        #pragma unroll 4
        for (int j = 0; j < D; ++j) a += as[j] * Wn[(size_t)j * (3 * D) + D + tid];
        heads_s[tid] = a;
    }
    __syncthreads();

    {
        float a = 0.f;
        #pragma unroll 4
        for (int k = 0; k < D; ++k) a += heads_s[k] * Wo[k * D + tid];
        glimpse_s[tid] = a;
    }
    __syncthreads();

    {
        const float* wr = Wn + (size_t)tid * (3 * D) + 2 * D;
        float a = 0.f;
        #pragma unroll
        for (int dd = 0; dd < D; dd += 4) {
            float4 w4 = *(const float4*)(wr + dd);
            a += glimpse_s[dd + 0] * w4.x + glimpse_s[dd + 1] * w4.y
               + glimpse_s[dd + 2] * w4.z + glimpse_s[dd + 3] * w4.w;
        }
        g_gk[(size_t)b * D + tid] = a * 0.08838834764831845f;  // 1/sqrt(128)
    }
}

// ---------------------------------------------------------------------------
// Kernel 3a: logits slices. grid = BB*SPL (2048), 256 thr. 4 rows per
// warp-iter, packed dots, mask-predicated loads.
// ---------------------------------------------------------------------------
__global__ __launch_bounds__(256) void k_logits_part(
    const float* __restrict__ emb,
    const void*  __restrict__ mask,
    float*       __restrict__ out)
{
    __shared__ float gk_s[D];
    __shared__ unsigned char sh_mk[RPL];
    __shared__ float lg[RPL];
    __shared__ float red[256];

    const int bx   = blockIdx.x;
    const int b    = bx / SPL, c = bx % SPL;
    const int tid  = threadIdx.x;
    const int wid  = tid >> 5;
    const int lane = tid & 31;
    const int base = c * RPL;
    const float* E = emb + (size_t)b * NN * D;
    const int mint = g_mask_is_int;

    if (tid < D) gk_s[tid] = g_gk[(size_t)b * D + tid];
    for (int i = tid; i < RPL; i += 256)
        sh_mk[i] = mask_at(mask, b * NN + base + i, mint) ? 1 : 0;
    __syncthreads();
    const ulonglong2 gk2 = *(const ulonglong2*)&gk_s[lane * 4];

    float wmax = -3.0e38f;
    #pragma unroll
    for (int it = 0; it < 4; ++it) {
        const int r = wid * 4 + it * 32;      // <= 124
        const bool va1 = (r + 1 < RPL), va2 = (r + 2 < RPL), va3 = (r + 3 < RPL);
        const bool m0 = (sh_mk[r] != 0);
        const bool m1 = va1 ? (sh_mk[r + 1] != 0) : true;
        const bool m2 = va2 ? (sh_mk[r + 2] != 0) : true;
        const bool m3 = va3 ? (sh_mk[r + 3] != 0) : true;

        ulonglong2 z2; z2.x = 0ull; z2.y = 0ull;
        ulonglong2 e0 = (!m0) ? *(const ulonglong2*)(E + (size_t)(base + r    ) * D + lane * 4) : z2;
        ulonglong2 e1 = (!m1) ? *(const ulonglong2*)(E + (size_t)(base + r + 1) * D + lane * 4) : z2;
        ulonglong2 e2 = (!m2) ? *(const ulonglong2*)(E + (size_t)(base + r + 2) * D + lane * 4) : z2;
        ulonglong2 e3 = (!m3) ? *(const ulonglong2*)(E + (size_t)(base + r + 3) * D + lane * 4) : z2;

        float p[4];
        p[0] = lohi_(fma2_(e0.y, gk2.y, mul2_(e0.x, gk2.x)));
        p[1] = lohi_(fma2_(e1.y, gk2.y, mul2_(e1.x, gk2.x)));
        p[2] = lohi_(fma2_(e2.y, gk2.y, mul2_(e2.x, gk2.x)));
        p[3] = lohi_(fma2_(e3.y, gk2.y, mul2_(e3.x, gk2.x)));

        // 4 sums over 32 lanes in 6 shuffles; value v = 2*b16 + b8 of lane.
        #pragma unroll
        for (int i = 0; i < 2; ++i) {
            float send = (lane & 16) ? p[i] : p[i + 2];
            float recv = __shfl_xor_sync(0xffffffffu, send, 16);
            p[i] = ((lane & 16) ? p[i + 2] : p[i]) + recv;
        }
        {
            float send = (lane & 8) ? p[0] : p[1];
            float recv = __shfl_xor_sync(0xffffffffu, send, 8);
            p[0] = ((lane & 8) ? p[1] : p[0]) + recv;
        }
        p[0] += __shfl_xor_sync(0xffffffffu, p[0], 4);
        p[0] += __shfl_xor_sync(0xffffffffu, p[0], 2);
        p[0] += __shfl_xor_sync(0xffffffffu, p[0], 1);

        const int v   = ((lane & 16) ? 2 : 0) | ((lane & 8) ? 1 : 0);
        const int row = r + v;
        if (row < RPL) {
            const bool mm = (sh_mk[row] != 0);
            const float val = mm ? NEGV : tanhf(p[0]) * 10.0f;
            wmax = fmaxf(wmax, val);
            if ((lane & 7) == 0) lg[row] = val;
        }
    }

    red[tid] = wmax;
    __syncthreads();
    #pragma unroll
    for (int st = 128; st > 0; st >>= 1) {
        if (tid < st) red[tid] = fmaxf(red[tid], red[tid + st]);
        __syncthreads();
    }
    const float M = red[0];
    __syncthreads();

    red[tid] = (tid < RPL) ? __expf(lg[tid] - M) : 0.f;   // RPL=125 <= 256
    __syncthreads();
    #pragma unroll
    for (int st = 128; st > 0; st >>= 1) {
        if (tid < st) red[tid] += red[tid + st];
        __syncthreads();
    }

    if (tid == 0) { g_lmax[bx] = M; g_lsum[bx] = red[0]; }
    for (int i = tid; i < RPL; i += 256) out[b * NN + base + i] = lg[i];
}

// ---------------------------------------------------------------------------
// Kernel 3b: fold slice (max, sum) into lse; subtract in-place. grid = BB.
// ---------------------------------------------------------------------------
__global__ __launch_bounds__(256) void k_fix(float* __restrict__ out)
{
    __shared__ float lse_s;
    const int b = blockIdx.x, tid = threadIdx.x;
    if (tid == 0) {
        float M = -3.0e38f;
        #pragma unroll
        for (int c = 0; c < SPL; ++c) M = fmaxf(M, g_lmax[b * SPL + c]);
        float S = 0.f;
        #pragma unroll
        for (int c = 0; c < SPL; ++c) S += g_lsum[b * SPL + c] * __expf(g_lmax[b * SPL + c] - M);
        lse_s = M + __logf(S);
    }
    __syncthreads();
    const float lse = lse_s;
    for (int i = tid; i < NN; i += 256) out[b * NN + i] -= lse;
}

// ---------------------------------------------------------------------------
// Launch. Inputs (metadata order): embeddings, W_node, W_fixed, W_step,
// W_out, first_idx, last_idx, mask. Output: float32 [256,1000].
// ---------------------------------------------------------------------------
extern "C" void kernel_launch(void* const* d_in, const int* in_sizes, int n_in,
                              void* d_out, int out_size)
{
    const float* emb  = (const float*)d_in[0];
    const float* Wn   = (const float*)d_in[1];
    const float* Wf   = (const float*)d_in[2];
    const float* Ws   = (const float*)d_in[3];
    const float* Wo   = (const float*)d_in[4];
    const int*   fi   = (const int*)d_in[5];
    const int*   li   = (const int*)d_in[6];
    const void*  mask = d_in[7];
    float*       out  = (float*)d_out;

    k_mean_part   <<<BB * SPM, 256>>>(emb, (const unsigned int*)mask);
    k_qprep       <<<BB, 256>>>(emb, Wf, Ws, Wn, fi, li);
    k_glimpse_part<<<BB * SPG, 256>>>(emb, mask);
    k_gmerge      <<<BB, 128>>>(Wn, Wo);
    k_logits_part <<<BB * SPL, 256>>>(emb, mask, out);
    k_fix         <<<BB, 256>>>(out);
}